// round 1
// baseline (speedup 1.0000x reference)
#include <cuda_runtime.h>
#include <math.h>

// Problem shape (hardcoded from reference): q,k,v [B,H,L,D] fp32, valid_lens [B] int32
#define B_DIM 2
#define H_DIM 16
#define L_DIM 2048
#define D_DIM 128

constexpr int BM = 64;           // query rows per CTA
constexpr int BN = 64;           // key rows per tile
constexpr int NT = 256;          // threads per CTA (16x16 fragment grid)
constexpr int DP = D_DIM + 4;    // padded smem row stride for Q/K/V tiles
constexpr int PSP = BN + 4;      // padded smem row stride for P tile

// smem: Qs[BM][DP] + Ks[BN][DP] + Vs[BN][DP] + Ps[BM][PSP]
constexpr int SMEM_FLOATS = BM * DP + BN * DP + BN * DP + BM * PSP;
constexpr int SMEM_BYTES  = SMEM_FLOATS * 4;   // 118784 B

__global__ __launch_bounds__(NT, 1)
void attn_fp32_flash_kernel(const float* __restrict__ Q,
                            const float* __restrict__ K,
                            const float* __restrict__ V,
                            const int*   __restrict__ VL,
                            float*       __restrict__ Out)
{
    extern __shared__ float sm[];
    float* Qs = sm;                    // [BM][DP]
    float* Ks = Qs + BM * DP;          // [BN][DP]
    float* Vs = Ks + BN * DP;          // [BN][DP]
    float* Ps = Vs + BN * DP;          // [BM][PSP]

    const int tid   = threadIdx.x;
    const int bh    = blockIdx.y;               // fused (b,h)
    const int qrow0 = blockIdx.x * BM;
    const int b     = bh / H_DIM;

    const int vl  = VL[b];                      // 1..L
    const int nkt = (vl + BN - 1) / BN;         // tiles with at least one valid key

    const int tr  = tid >> 4;                   // 0..15 (row group)
    const int tc  = tid & 15;                   // 0..15 (col group)
    const int tr4 = tr * 4;
    const int tc4 = tc * 4;

    const float scale = 0.08838834764831845f;   // 1/sqrt(128)

    // ---- load Q tile (scaled), natural [row][d] layout, coalesced ----
    const float* qg = Q + ((long)bh * L_DIM + qrow0) * D_DIM;
    #pragma unroll
    for (int it = 0; it < (BM * D_DIM / 4) / NT; ++it) {
        int f   = tid + it * NT;
        int row = f >> 5;          // D/4 = 32 float4 per row
        int dc  = f & 31;
        float4 x = ((const float4*)qg)[f];
        x.x *= scale; x.y *= scale; x.z *= scale; x.w *= scale;
        *(float4*)&Qs[row * DP + dc * 4] = x;
    }

    float m[4], l[4], acc[4][8];
    #pragma unroll
    for (int i = 0; i < 4; ++i) {
        m[i] = -1e30f;
        l[i] = 0.0f;
        #pragma unroll
        for (int j = 0; j < 8; ++j) acc[i][j] = 0.0f;
    }

    for (int kt = 0; kt < nkt; ++kt) {
        const float* kg = K + ((long)bh * L_DIM + kt * BN) * D_DIM;
        const float* vg = V + ((long)bh * L_DIM + kt * BN) * D_DIM;

        __syncthreads();   // prior-iter readers of Ks/Vs are done
        #pragma unroll
        for (int it = 0; it < (BN * D_DIM / 4) / NT; ++it) {
            int f   = tid + it * NT;
            int row = f >> 5;
            int dc  = f & 31;
            *(float4*)&Ks[row * DP + dc * 4] = ((const float4*)kg)[f];
            *(float4*)&Vs[row * DP + dc * 4] = ((const float4*)vg)[f];
        }
        __syncthreads();

        // ---- S = (Q*scale) @ K^T : 4x4 fragment per thread ----
        float s[4][4];
        #pragma unroll
        for (int i = 0; i < 4; ++i)
            #pragma unroll
            for (int j = 0; j < 4; ++j) s[i][j] = 0.0f;

        #pragma unroll 4
        for (int dc = 0; dc < D_DIM / 4; ++dc) {
            float4 qf[4], kf[4];
            #pragma unroll
            for (int i = 0; i < 4; ++i)
                qf[i] = *(const float4*)&Qs[(tr4 + i) * DP + dc * 4];
            #pragma unroll
            for (int j = 0; j < 4; ++j)
                kf[j] = *(const float4*)&Ks[(tc4 + j) * DP + dc * 4];
            #pragma unroll
            for (int i = 0; i < 4; ++i)
                #pragma unroll
                for (int j = 0; j < 4; ++j) {
                    s[i][j] += qf[i].x * kf[j].x;
                    s[i][j] += qf[i].y * kf[j].y;
                    s[i][j] += qf[i].z * kf[j].z;
                    s[i][j] += qf[i].w * kf[j].w;
                }
        }

        // ---- key mask (only the boundary tile can have invalid cols) ----
        if (kt == nkt - 1) {
            int colb = kt * BN + tc4;
            #pragma unroll
            for (int j = 0; j < 4; ++j) {
                if (colb + j >= vl) {
                    #pragma unroll
                    for (int i = 0; i < 4; ++i) s[i][j] = -1e9f;
                }
            }
        }

        // ---- online softmax update (row stats live in 16-lane groups) ----
        #pragma unroll
        for (int i = 0; i < 4; ++i) {
            float rm = fmaxf(fmaxf(s[i][0], s[i][1]), fmaxf(s[i][2], s[i][3]));
            rm = fmaxf(rm, __shfl_xor_sync(0xffffffffu, rm, 8));
            rm = fmaxf(rm, __shfl_xor_sync(0xffffffffu, rm, 4));
            rm = fmaxf(rm, __shfl_xor_sync(0xffffffffu, rm, 2));
            rm = fmaxf(rm, __shfl_xor_sync(0xffffffffu, rm, 1));

            float mn   = fmaxf(m[i], rm);
            float corr = __expf(m[i] - mn);
            m[i] = mn;

            float p0 = __expf(s[i][0] - mn);
            float p1 = __expf(s[i][1] - mn);
            float p2 = __expf(s[i][2] - mn);
            float p3 = __expf(s[i][3] - mn);
            s[i][0] = p0; s[i][1] = p1; s[i][2] = p2; s[i][3] = p3;

            float rs = (p0 + p1) + (p2 + p3);
            rs += __shfl_xor_sync(0xffffffffu, rs, 8);
            rs += __shfl_xor_sync(0xffffffffu, rs, 4);
            rs += __shfl_xor_sync(0xffffffffu, rs, 2);
            rs += __shfl_xor_sync(0xffffffffu, rs, 1);

            l[i] = l[i] * corr + rs;
            #pragma unroll
            for (int jj = 0; jj < 8; ++jj) acc[i][jj] *= corr;
        }

        // ---- stash P row-major; only warp-local visibility needed ----
        #pragma unroll
        for (int i = 0; i < 4; ++i) {
            float4 pf = make_float4(s[i][0], s[i][1], s[i][2], s[i][3]);
            *(float4*)&Ps[(tr4 + i) * PSP + tc4] = pf;
        }
        __syncwarp();

        // ---- O += P @ V : each thread owns 4 rows x 8 cols of O ----
        #pragma unroll 4
        for (int kk = 0; kk < BN; ++kk) {
            float4 v0 = *(const float4*)&Vs[kk * DP + tc * 8];
            float4 v1 = *(const float4*)&Vs[kk * DP + tc * 8 + 4];
            #pragma unroll
            for (int i = 0; i < 4; ++i) {
                float pv = Ps[(tr4 + i) * PSP + kk];
                acc[i][0] += pv * v0.x;
                acc[i][1] += pv * v0.y;
                acc[i][2] += pv * v0.z;
                acc[i][3] += pv * v0.w;
                acc[i][4] += pv * v1.x;
                acc[i][5] += pv * v1.y;
                acc[i][6] += pv * v1.z;
                acc[i][7] += pv * v1.w;
            }
        }
    }

    // ---- epilogue: normalize and store ----
    float* og = Out + ((long)bh * L_DIM + qrow0) * D_DIM;
    #pragma unroll
    for (int i = 0; i < 4; ++i) {
        float inv = 1.0f / l[i];
        float4 o0 = make_float4(acc[i][0] * inv, acc[i][1] * inv,
                                acc[i][2] * inv, acc[i][3] * inv);
        float4 o1 = make_float4(acc[i][4] * inv, acc[i][5] * inv,
                                acc[i][6] * inv, acc[i][7] * inv);
        *(float4*)&og[(tr4 + i) * D_DIM + tc * 8]     = o0;
        *(float4*)&og[(tr4 + i) * D_DIM + tc * 8 + 4] = o1;
    }
}

extern "C" void kernel_launch(void* const* d_in, const int* in_sizes, int n_in,
                              void* d_out, int out_size)
{
    const float* q  = (const float*)d_in[0];
    const float* k  = (const float*)d_in[1];
    const float* v  = (const float*)d_in[2];
    const int*   vl = (const int*)d_in[3];
    float*       o  = (float*)d_out;

    // Idempotent, deterministic, not a stream op — safe under graph capture.
    cudaFuncSetAttribute(attn_fp32_flash_kernel,
                         cudaFuncAttributeMaxDynamicSharedMemorySize, SMEM_BYTES);

    dim3 grid(L_DIM / BM, B_DIM * H_DIM);
    attn_fp32_flash_kernel<<<grid, NT, SMEM_BYTES>>>(q, k, v, vl, o);
}

// round 2
// speedup vs baseline: 1.6894x; 1.6894x over previous
#include <cuda_runtime.h>
#include <math.h>

#define B_DIM 2
#define H_DIM 16
#define L_DIM 2048
#define D_DIM 128

constexpr int BM = 64;           // query rows per CTA
constexpr int BN = 64;           // key rows per tile
constexpr int NT = 256;          // 16x16 fragment grid
constexpr int ROWF = 128;        // floats per smem row (no padding; swizzled)

// smem: Qs[64][128] + Ks[64][128] + Vs[64][128] + Ps[64][64]  (floats)
constexpr int SMEM_FLOATS = 3 * BM * ROWF + BM * BN;
constexpr int SMEM_BYTES  = SMEM_FLOATS * 4;   // 114688 B -> 2 CTAs/SM

// swizzled float-offset of float4-chunk c (0..31) in row r
__device__ __forceinline__ int swz(int r, int c) {
    return r * ROWF + ((c ^ ((r >> 2) & 7)) << 2);
}

__global__ __launch_bounds__(NT, 2)
void attn_fp32_flash2_kernel(const float* __restrict__ Q,
                             const float* __restrict__ K,
                             const float* __restrict__ V,
                             const int*   __restrict__ VL,
                             float*       __restrict__ Out)
{
    extern __shared__ float sm[];
    float* Qs = sm;                       // [64][128] swizzled
    float* Ks = Qs + BM * ROWF;           // [64][128] swizzled
    float* Vs = Ks + BM * ROWF;           // [64][128] swizzled
    float* Ps = Vs + BM * ROWF;           // [64][64] linear

    const int tid   = threadIdx.x;
    const int bh    = blockIdx.y;
    const int qrow0 = blockIdx.x * BM;
    const int b     = bh / H_DIM;

    const int vl  = VL[b];
    const int nkt = (vl + BN - 1) / BN;

    const int tr  = tid >> 4;     // 0..15
    const int tc  = tid & 15;     // 0..15
    const int tr4 = tr * 4;
    const int tc4 = tc * 4;
    const int sq  = tr & 7;       // swizzle const for Q-frag rows (tr4+i)>>2 == tr
    const int sk  = tc & 7;       // swizzle const for K-frag rows (tc4+j)>>2 == tc

    const float scale = 0.08838834764831845f;   // 1/sqrt(128)

    // ---- load Q tile (scaled) into swizzled smem ----
    const float* qg = Q + ((long)bh * L_DIM + qrow0) * D_DIM;
    #pragma unroll
    for (int it = 0; it < (BM * D_DIM / 4) / NT; ++it) {
        int f   = tid + it * NT;
        int row = f >> 5;          // 32 float4-chunks per row
        int c   = f & 31;
        float4 x = ((const float4*)qg)[f];
        x.x *= scale; x.y *= scale; x.z *= scale; x.w *= scale;
        *(float4*)&Qs[swz(row, c)] = x;
    }

    float m[4], l[4], acc[4][8];
    #pragma unroll
    for (int i = 0; i < 4; ++i) {
        m[i] = -1e30f; l[i] = 0.0f;
        #pragma unroll
        for (int j = 0; j < 8; ++j) acc[i][j] = 0.0f;
    }

    for (int kt = 0; kt < nkt; ++kt) {
        const float* kg = K + ((long)bh * L_DIM + kt * BN) * D_DIM;
        const float* vg = V + ((long)bh * L_DIM + kt * BN) * D_DIM;

        __syncthreads();
        #pragma unroll
        for (int it = 0; it < (BN * D_DIM / 4) / NT; ++it) {
            int f   = tid + it * NT;
            int row = f >> 5;
            int c   = f & 31;
            *(float4*)&Ks[swz(row, c)] = ((const float4*)kg)[f];
            *(float4*)&Vs[swz(row, c)] = ((const float4*)vg)[f];
        }
        __syncthreads();

        // ---- S = Qs @ Ks^T : 4x4 fragments, swizzled conflict-free loads ----
        float s[4][4];
        #pragma unroll
        for (int i = 0; i < 4; ++i)
            #pragma unroll
            for (int j = 0; j < 4; ++j) s[i][j] = 0.0f;

        #pragma unroll 8
        for (int dc = 0; dc < D_DIM / 4; ++dc) {
            const int oq = (dc ^ sq) << 2;   // same chunk offset for all 4 Q rows
            const int ok = (dc ^ sk) << 2;   // same chunk offset for all 4 K rows
            float4 qf[4], kf[4];
            #pragma unroll
            for (int i = 0; i < 4; ++i)
                qf[i] = *(const float4*)&Qs[(tr4 + i) * ROWF + oq];
            #pragma unroll
            for (int j = 0; j < 4; ++j)
                kf[j] = *(const float4*)&Ks[(tc4 + j) * ROWF + ok];
            #pragma unroll
            for (int i = 0; i < 4; ++i)
                #pragma unroll
                for (int j = 0; j < 4; ++j) {
                    s[i][j] += qf[i].x * kf[j].x;
                    s[i][j] += qf[i].y * kf[j].y;
                    s[i][j] += qf[i].z * kf[j].z;
                    s[i][j] += qf[i].w * kf[j].w;
                }
        }

        // ---- key mask: only boundary tile can be partial ----
        if (kt == nkt - 1) {
            int colb = kt * BN + tc4;
            #pragma unroll
            for (int j = 0; j < 4; ++j) {
                if (colb + j >= vl) {
                    #pragma unroll
                    for (int i = 0; i < 4; ++i) s[i][j] = -1e9f;
                }
            }
        }

        // ---- online softmax (row stats across 16-lane groups) ----
        #pragma unroll
        for (int i = 0; i < 4; ++i) {
            float rm = fmaxf(fmaxf(s[i][0], s[i][1]), fmaxf(s[i][2], s[i][3]));
            rm = fmaxf(rm, __shfl_xor_sync(0xffffffffu, rm, 8));
            rm = fmaxf(rm, __shfl_xor_sync(0xffffffffu, rm, 4));
            rm = fmaxf(rm, __shfl_xor_sync(0xffffffffu, rm, 2));
            rm = fmaxf(rm, __shfl_xor_sync(0xffffffffu, rm, 1));

            float mn   = fmaxf(m[i], rm);
            float corr = __expf(m[i] - mn);
            m[i] = mn;

            float p0 = __expf(s[i][0] - mn);
            float p1 = __expf(s[i][1] - mn);
            float p2 = __expf(s[i][2] - mn);
            float p3 = __expf(s[i][3] - mn);
            s[i][0] = p0; s[i][1] = p1; s[i][2] = p2; s[i][3] = p3;

            float rs = (p0 + p1) + (p2 + p3);
            rs += __shfl_xor_sync(0xffffffffu, rs, 8);
            rs += __shfl_xor_sync(0xffffffffu, rs, 4);
            rs += __shfl_xor_sync(0xffffffffu, rs, 2);
            rs += __shfl_xor_sync(0xffffffffu, rs, 1);

            l[i] = l[i] * corr + rs;
            #pragma unroll
            for (int jj = 0; jj < 8; ++jj) acc[i][jj] *= corr;
        }

        // ---- stash P rows (warp-private rows; warp-local visibility) ----
        #pragma unroll
        for (int i = 0; i < 4; ++i)
            *(float4*)&Ps[(tr4 + i) * BN + tc4] =
                make_float4(s[i][0], s[i][1], s[i][2], s[i][3]);
        __syncwarp();

        // ---- O += P @ V : P via float4 broadcast, V via swizzled loads ----
        #pragma unroll 4
        for (int kb = 0; kb < BN / 4; ++kb) {
            float4 pf[4];
            #pragma unroll
            for (int i = 0; i < 4; ++i)
                pf[i] = *(const float4*)&Ps[(tr4 + i) * BN + kb * 4];

            #pragma unroll
            for (int u = 0; u < 4; ++u) {
                int kk = kb * 4 + u;
                int sv = (kk >> 2) & 7;
                float4 v0 = *(const float4*)&Vs[kk * ROWF + (((2 * tc)     ^ sv) << 2)];
                float4 v1 = *(const float4*)&Vs[kk * ROWF + (((2 * tc + 1) ^ sv) << 2)];
                #pragma unroll
                for (int i = 0; i < 4; ++i) {
                    float pv = (u == 0) ? pf[i].x : (u == 1) ? pf[i].y
                             : (u == 2) ? pf[i].z : pf[i].w;
                    acc[i][0] += pv * v0.x;
                    acc[i][1] += pv * v0.y;
                    acc[i][2] += pv * v0.z;
                    acc[i][3] += pv * v0.w;
                    acc[i][4] += pv * v1.x;
                    acc[i][5] += pv * v1.y;
                    acc[i][6] += pv * v1.z;
                    acc[i][7] += pv * v1.w;
                }
            }
        }
    }

    // ---- epilogue ----
    float* og = Out + ((long)bh * L_DIM + qrow0) * D_DIM;
    #pragma unroll
    for (int i = 0; i < 4; ++i) {
        float inv = 1.0f / l[i];
        *(float4*)&og[(tr4 + i) * D_DIM + tc * 8] =
            make_float4(acc[i][0] * inv, acc[i][1] * inv,
                        acc[i][2] * inv, acc[i][3] * inv);
        *(float4*)&og[(tr4 + i) * D_DIM + tc * 8 + 4] =
            make_float4(acc[i][4] * inv, acc[i][5] * inv,
                        acc[i][6] * inv, acc[i][7] * inv);
    }
}

extern "C" void kernel_launch(void* const* d_in, const int* in_sizes, int n_in,
                              void* d_out, int out_size)
{
    const float* q  = (const float*)d_in[0];
    const float* k  = (const float*)d_in[1];
    const float* v  = (const float*)d_in[2];
    const int*   vl = (const int*)d_in[3];
    float*       o  = (float*)d_out;

    cudaFuncSetAttribute(attn_fp32_flash2_kernel,
                         cudaFuncAttributeMaxDynamicSharedMemorySize, SMEM_BYTES);

    dim3 grid(L_DIM / BM, B_DIM * H_DIM);
    attn_fp32_flash2_kernel<<<grid, NT, SMEM_BYTES>>>(q, k, v, vl, o);
}